// round 1
// baseline (speedup 1.0000x reference)
#include <cuda_runtime.h>

#define B_SZ    2
#define S_LEN   2048
#define D_MODEL 1024
#define NHEADS  16
#define DK      64
#define M_ROWS  (B_SZ * S_LEN)     // 4096
#define QKV_N   (3 * D_MODEL)      // 3072

// Scratch (alloc-free: __device__ globals)
__device__ float g_qkv[(size_t)M_ROWS * QKV_N];   // (b*s, 3*d)
__device__ float g_ctx[(size_t)M_ROWS * D_MODEL]; // (b*s, d) already head-interleaved

// ---------------------------------------------------------------------------
// Classic 128x128x8 register-blocked SGEMM. 256 threads, 8x8 micro-tile.
// C[M,N] = A[M,K] @ B[K,N] + bias[N].  M,N multiples of 128, K multiple of 8.
// ---------------------------------------------------------------------------
__device__ __forceinline__ void sgemm_body(const float* __restrict__ A,
                                           const float* __restrict__ B,
                                           const float* __restrict__ bias,
                                           float* __restrict__ C,
                                           int M, int N, int K)
{
    __shared__ float As[8][128];   // transposed A tile
    __shared__ float Bs[8][128];

    const int tid = threadIdx.x;
    const int tx  = tid & 15;
    const int ty  = tid >> 4;
    const int bm  = blockIdx.y * 128;
    const int bn  = blockIdx.x * 128;

    const int aRow = tid >> 1;          // 0..127
    const int aCol = (tid & 1) << 2;    // 0 or 4
    const int bRow = tid >> 5;          // 0..7
    const int bCol = (tid & 31) << 2;   // 0..124

    const float* Aptr = A + (size_t)(bm + aRow) * K + aCol;
    const float* Bptr = B + (size_t)bRow * N + (bn + bCol);

    float acc[8][8];
    #pragma unroll
    for (int i = 0; i < 8; i++)
        #pragma unroll
        for (int j = 0; j < 8; j++) acc[i][j] = 0.f;

    for (int k0 = 0; k0 < K; k0 += 8) {
        float4 av = *(const float4*)Aptr;
        float4 bv = *(const float4*)Bptr;
        __syncthreads();
        As[aCol + 0][aRow] = av.x;
        As[aCol + 1][aRow] = av.y;
        As[aCol + 2][aRow] = av.z;
        As[aCol + 3][aRow] = av.w;
        *(float4*)(&Bs[bRow][bCol]) = bv;
        __syncthreads();
        Aptr += 8;
        Bptr += (size_t)8 * N;

        #pragma unroll
        for (int kk = 0; kk < 8; kk++) {
            float a[8], b[8];
            *(float4*)(a)     = *(const float4*)(&As[kk][ty * 8]);
            *(float4*)(a + 4) = *(const float4*)(&As[kk][ty * 8 + 4]);
            *(float4*)(b)     = *(const float4*)(&Bs[kk][tx * 8]);
            *(float4*)(b + 4) = *(const float4*)(&Bs[kk][tx * 8 + 4]);
            #pragma unroll
            for (int i = 0; i < 8; i++)
                #pragma unroll
                for (int j = 0; j < 8; j++)
                    acc[i][j] += a[i] * b[j];
        }
    }

    #pragma unroll
    for (int i = 0; i < 8; i++) {
        int row = bm + ty * 8 + i;
        #pragma unroll
        for (int j = 0; j < 8; j += 4) {
            int col = bn + tx * 8 + j;
            float4 r;
            r.x = acc[i][j + 0] + bias[col + 0];
            r.y = acc[i][j + 1] + bias[col + 1];
            r.z = acc[i][j + 2] + bias[col + 2];
            r.w = acc[i][j + 3] + bias[col + 3];
            *(float4*)(&C[(size_t)row * N + col]) = r;
        }
    }
}

__global__ void __launch_bounds__(256)
k_gemm_qkv(const float* __restrict__ x, const float* __restrict__ W,
           const float* __restrict__ bias)
{
    sgemm_body(x, W, bias, g_qkv, M_ROWS, QKV_N, D_MODEL);
}

__global__ void __launch_bounds__(256)
k_gemm_out(const float* __restrict__ W, const float* __restrict__ bias,
           float* __restrict__ out)
{
    sgemm_body(g_ctx, W, bias, out, M_ROWS, D_MODEL, D_MODEL);
}

// ---------------------------------------------------------------------------
// Flash-attention style: 1 thread = 1 query row (q,o register-resident),
// K/V tiles of 64 keys staged in smem, online softmax.
// qkv layout per row (3*d): head h occupies columns [h*192, h*192+192):
//   q = [h*192, +64), k = [h*192+64, +64), v = [h*192+128, +64)
// ctx written as (b, s, h*64+dd) -> matches transpose(0,2,1,3).reshape.
// ---------------------------------------------------------------------------
#define ATT_BM 128
#define ATT_BN 64

__global__ void __launch_bounds__(ATT_BM)
k_attn()
{
    __shared__ float Ks[ATT_BN][DK];
    __shared__ float Vs[ATT_BN][DK];

    const int bh  = blockIdx.x;       // 0..31
    const int b   = bh >> 4;
    const int h   = bh & 15;
    const int tid = threadIdx.x;
    const int qrow = blockIdx.y * ATT_BM + tid;

    const float* base = g_qkv + (size_t)b * S_LEN * QKV_N;
    const float* qptr = base + (size_t)qrow * QKV_N + h * (3 * DK);

    float q[DK], o[DK];
    #pragma unroll
    for (int c = 0; c < DK / 4; c++) {
        float4 t = ((const float4*)qptr)[c];
        q[4 * c + 0] = t.x; q[4 * c + 1] = t.y;
        q[4 * c + 2] = t.z; q[4 * c + 3] = t.w;
    }
    #pragma unroll
    for (int d = 0; d < DK; d++) o[d] = 0.f;

    float m = -1e30f, l = 0.f;
    const float inv_scale = 0.125f;   // 1/sqrt(64)

    for (int kt = 0; kt < S_LEN; kt += ATT_BN) {
        __syncthreads();
        // cooperative load of K,V tiles (coalesced: 16 consecutive threads per row)
        #pragma unroll
        for (int idx = tid; idx < ATT_BN * (DK / 4); idx += ATT_BM) {
            int r = idx >> 4;     // key row within tile
            int c = idx & 15;     // float4 column
            const float* kp = base + (size_t)(kt + r) * QKV_N + h * (3 * DK) + DK;
            ((float4*)&Ks[r][0])[c] = ((const float4*)kp)[c];
            ((float4*)&Vs[r][0])[c] = ((const float4*)(kp + DK))[c];
        }
        __syncthreads();

        #pragma unroll 1
        for (int j = 0; j < ATT_BN; j++) {
            const float4* k4 = (const float4*)&Ks[j][0];
            float s0 = 0.f, s1 = 0.f, s2 = 0.f, s3 = 0.f;
            #pragma unroll
            for (int c = 0; c < 16; c += 4) {
                float4 kv0 = k4[c + 0];
                float4 kv1 = k4[c + 1];
                float4 kv2 = k4[c + 2];
                float4 kv3 = k4[c + 3];
                s0 += q[4*c+ 0]*kv0.x + q[4*c+ 1]*kv0.y + q[4*c+ 2]*kv0.z + q[4*c+ 3]*kv0.w;
                s1 += q[4*c+ 4]*kv1.x + q[4*c+ 5]*kv1.y + q[4*c+ 6]*kv1.z + q[4*c+ 7]*kv1.w;
                s2 += q[4*c+ 8]*kv2.x + q[4*c+ 9]*kv2.y + q[4*c+10]*kv2.z + q[4*c+11]*kv2.w;
                s3 += q[4*c+12]*kv3.x + q[4*c+13]*kv3.y + q[4*c+14]*kv3.z + q[4*c+15]*kv3.w;
            }
            float s = ((s0 + s1) + (s2 + s3)) * inv_scale;

            if (s > m) {                 // rare after warmup; rescale running state
                float corr = __expf(m - s);
                m = s;
                l *= corr;
                #pragma unroll
                for (int d = 0; d < DK; d++) o[d] *= corr;
            }
            float p = __expf(s - m);
            l += p;

            const float4* v4 = (const float4*)&Vs[j][0];
            #pragma unroll
            for (int c = 0; c < 16; c++) {
                float4 vv = v4[c];
                o[4*c+0] += p * vv.x;
                o[4*c+1] += p * vv.y;
                o[4*c+2] += p * vv.z;
                o[4*c+3] += p * vv.w;
            }
        }
    }

    float invl = 1.0f / l;
    float* op = g_ctx + (size_t)(b * S_LEN + qrow) * D_MODEL + h * DK;
    #pragma unroll
    for (int c = 0; c < 16; c++) {
        float4 r;
        r.x = o[4*c+0] * invl;
        r.y = o[4*c+1] * invl;
        r.z = o[4*c+2] * invl;
        r.w = o[4*c+3] * invl;
        ((float4*)op)[c] = r;
    }
}

// ---------------------------------------------------------------------------
extern "C" void kernel_launch(void* const* d_in, const int* in_sizes, int n_in,
                              void* d_out, int out_size)
{
    (void)in_sizes; (void)n_in; (void)out_size;
    const float* x     = (const float*)d_in[0];
    const float* W_qkv = (const float*)d_in[1];
    const float* b_qkv = (const float*)d_in[2];
    const float* W_o   = (const float*)d_in[3];
    const float* b_o   = (const float*)d_in[4];
    float* out = (float*)d_out;

    k_gemm_qkv<<<dim3(QKV_N / 128, M_ROWS / 128), 256>>>(x, W_qkv, b_qkv);
    k_attn<<<dim3(B_SZ * NHEADS, S_LEN / ATT_BM), ATT_BM>>>();
    k_gemm_out<<<dim3(D_MODEL / 128, M_ROWS / 128), 256>>>(W_o, b_o, out);
}

// round 2
// speedup vs baseline: 4.2908x; 4.2908x over previous
#include <cuda_runtime.h>

#define B_SZ    2
#define S_LEN   2048
#define D_MODEL 1024
#define NHEADS  16
#define DK      64
#define M_ROWS  (B_SZ * S_LEN)     // 4096
#define QKV_N   (3 * D_MODEL)      // 3072

// Scratch (alloc-free: __device__ globals)
__device__ float g_qkv[(size_t)M_ROWS * QKV_N];   // (b*s, 3*d)
__device__ float g_ctx[(size_t)M_ROWS * D_MODEL]; // (b*s, d) head-interleaved

// ---------------------------------------------------------------------------
// helpers
// ---------------------------------------------------------------------------
__device__ __forceinline__ unsigned f2tf(float f) {
    unsigned u;
    asm("cvt.rna.tf32.f32 %0, %1;" : "=r"(u) : "f"(f));
    return u;
}

__device__ __forceinline__ void mma_tf32(float* c, const unsigned* a,
                                         unsigned b0, unsigned b1) {
    asm volatile(
        "mma.sync.aligned.m16n8k8.row.col.f32.tf32.tf32.f32 "
        "{%0,%1,%2,%3}, {%4,%5,%6,%7}, {%8,%9}, {%0,%1,%2,%3};\n"
        : "+f"(c[0]), "+f"(c[1]), "+f"(c[2]), "+f"(c[3])
        : "r"(a[0]), "r"(a[1]), "r"(a[2]), "r"(a[3]), "r"(b0), "r"(b1));
}

// ---------------------------------------------------------------------------
// TF32 GEMM: C[M,N] = A[M,K] @ B[K,N] + bias[N]
// Block 128x128, BK=16, 256 threads = 8 warps (4 along M, 2 along N),
// warp tile 32x64. Double-buffered smem. Padded strides:
//   As stride 20  (== 4 mod 32): A-frag loads conflict-free
//   Bs stride 136 (== 8 mod 32): B-frag loads conflict-free
// ---------------------------------------------------------------------------
#define AS_STR 20
#define BS_STR 136

__device__ __forceinline__ void gemm_tf32_body(const float* __restrict__ A,
                                               const float* __restrict__ B,
                                               const float* __restrict__ bias,
                                               float* __restrict__ C,
                                               int M, int N, int K)
{
    __shared__ unsigned As[2][128 * AS_STR];
    __shared__ unsigned Bs[2][16 * BS_STR];

    const int tid  = threadIdx.x;
    const int wid  = tid >> 5;
    const int lane = tid & 31;
    const int lr   = lane >> 2;   // 0..7
    const int lc   = lane & 3;    // 0..3
    const int wm   = (wid & 3) * 32;
    const int wn   = (wid >> 2) * 64;
    const int bm   = blockIdx.y * 128;
    const int bn   = blockIdx.x * 128;

    float acc[2][8][4];
    #pragma unroll
    for (int i = 0; i < 2; i++)
        #pragma unroll
        for (int j = 0; j < 8; j++)
            #pragma unroll
            for (int q = 0; q < 4; q++) acc[i][j][q] = 0.f;

    float4 aR[2], bR[2];

    // global-load index precompute
    const int aRow0 = tid >> 2,  aCv0 = tid & 3;           // f = tid
    const int aRow1 = (tid + 256) >> 2, aCv1 = tid & 3;    // f = tid+256
    const int bRow0 = tid >> 5,  bCv0 = tid & 31;
    const int bRow1 = (tid + 256) >> 5, bCv1 = tid & 31;

    auto ldg = [&](int k0) {
        aR[0] = *(const float4*)(A + (size_t)(bm + aRow0) * K + k0 + aCv0 * 4);
        aR[1] = *(const float4*)(A + (size_t)(bm + aRow1) * K + k0 + aCv1 * 4);
        bR[0] = *(const float4*)(B + (size_t)(k0 + bRow0) * N + bn + bCv0 * 4);
        bR[1] = *(const float4*)(B + (size_t)(k0 + bRow1) * N + bn + bCv1 * 4);
    };
    auto sts = [&](int buf) {
        unsigned* a0 = &As[buf][aRow0 * AS_STR + aCv0 * 4];
        a0[0] = f2tf(aR[0].x); a0[1] = f2tf(aR[0].y);
        a0[2] = f2tf(aR[0].z); a0[3] = f2tf(aR[0].w);
        unsigned* a1 = &As[buf][aRow1 * AS_STR + aCv1 * 4];
        a1[0] = f2tf(aR[1].x); a1[1] = f2tf(aR[1].y);
        a1[2] = f2tf(aR[1].z); a1[3] = f2tf(aR[1].w);
        unsigned* b0 = &Bs[buf][bRow0 * BS_STR + bCv0 * 4];
        b0[0] = f2tf(bR[0].x); b0[1] = f2tf(bR[0].y);
        b0[2] = f2tf(bR[0].z); b0[3] = f2tf(bR[0].w);
        unsigned* b1 = &Bs[buf][bRow1 * BS_STR + bCv1 * 4];
        b1[0] = f2tf(bR[1].x); b1[1] = f2tf(bR[1].y);
        b1[2] = f2tf(bR[1].z); b1[3] = f2tf(bR[1].w);
    };

    ldg(0);
    sts(0);
    __syncthreads();

    const int nT = K / 16;
    for (int t = 0; t < nT; t++) {
        const int buf = t & 1;
        const bool more = (t + 1 < nT);
        if (more) ldg((t + 1) * 16);

        #pragma unroll
        for (int kk = 0; kk < 2; kk++) {
            unsigned af[2][4];
            #pragma unroll
            for (int i = 0; i < 2; i++) {
                const int m = wm + 16 * i + lr;
                af[i][0] = As[buf][m * AS_STR + 8 * kk + lc];
                af[i][1] = As[buf][(m + 8) * AS_STR + 8 * kk + lc];
                af[i][2] = As[buf][m * AS_STR + 8 * kk + lc + 4];
                af[i][3] = As[buf][(m + 8) * AS_STR + 8 * kk + lc + 4];
            }
            #pragma unroll
            for (int j = 0; j < 8; j++) {
                const unsigned b0 = Bs[buf][(8 * kk + lc) * BS_STR + wn + 8 * j + lr];
                const unsigned b1 = Bs[buf][(8 * kk + lc + 4) * BS_STR + wn + 8 * j + lr];
                mma_tf32(acc[0][j], af[0], b0, b1);
                mma_tf32(acc[1][j], af[1], b0, b1);
            }
        }

        if (more) sts(buf ^ 1);
        __syncthreads();
    }

    // epilogue: bias + store
    #pragma unroll
    for (int j = 0; j < 8; j++) {
        const int col = bn + wn + 8 * j + 2 * lc;
        const float bs0 = bias[col], bs1 = bias[col + 1];
        #pragma unroll
        for (int i = 0; i < 2; i++) {
            const int row = bm + wm + 16 * i + lr;
            float2 r0 = make_float2(acc[i][j][0] + bs0, acc[i][j][1] + bs1);
            float2 r1 = make_float2(acc[i][j][2] + bs0, acc[i][j][3] + bs1);
            *(float2*)(C + (size_t)row * N + col) = r0;
            *(float2*)(C + (size_t)(row + 8) * N + col) = r1;
        }
    }
}

__global__ void __launch_bounds__(256)
k_gemm_qkv(const float* __restrict__ x, const float* __restrict__ W,
           const float* __restrict__ bias)
{
    gemm_tf32_body(x, W, bias, g_qkv, M_ROWS, QKV_N, D_MODEL);
}

__global__ void __launch_bounds__(256)
k_gemm_out(const float* __restrict__ W, const float* __restrict__ bias,
           float* __restrict__ out)
{
    gemm_tf32_body(g_ctx, W, bias, out, M_ROWS, D_MODEL, D_MODEL);
}

// ---------------------------------------------------------------------------
// Flash attention with tf32 tensor cores.
// Block = 128 threads (4 warps), 64 query rows; each warp owns 16 rows.
// Q fragments live in registers (scale 1/8 folded in). Per 64-key tile:
//   S = Q@K^T (mma) -> online softmax on C-fragments -> P bounced through
//   smem (aliased onto K buffer) to become A-fragments -> O += P@V (mma).
// Padded strides: K/P stride 68 (==4 mod 32), V stride 72 (==8 mod 32).
// ---------------------------------------------------------------------------
#define KS_STR 68
#define VS_STR 72

__global__ void __launch_bounds__(128)
k_attn_tc()
{
    __shared__ unsigned KPs[64 * KS_STR];  // K tile, reused as P buffer
    __shared__ unsigned Vs [64 * VS_STR];

    const int tid  = threadIdx.x;
    const int wid  = tid >> 5;
    const int lane = tid & 31;
    const int lr   = lane >> 2;
    const int lc   = lane & 3;
    const int bh   = blockIdx.x;
    const int b    = bh >> 4;
    const int h    = bh & 15;
    const int q0   = blockIdx.y * 64;

    const float* base = g_qkv + (size_t)b * S_LEN * QKV_N;
    const int ho = h * (3 * DK);

    // Q fragments (register-resident for whole kernel), pre-scaled by 1/8
    unsigned Qf[8][4];
    {
        const float* qr0 = base + (size_t)(q0 + wid * 16 + lr) * QKV_N + ho;
        const float* qr1 = qr0 + (size_t)8 * QKV_N;
        #pragma unroll
        for (int kk = 0; kk < 8; kk++) {
            Qf[kk][0] = f2tf(0.125f * qr0[8 * kk + lc]);
            Qf[kk][1] = f2tf(0.125f * qr1[8 * kk + lc]);
            Qf[kk][2] = f2tf(0.125f * qr0[8 * kk + lc + 4]);
            Qf[kk][3] = f2tf(0.125f * qr1[8 * kk + lc + 4]);
        }
    }

    float oAcc[8][4];
    #pragma unroll
    for (int j = 0; j < 8; j++)
        #pragma unroll
        for (int q = 0; q < 4; q++) oAcc[j][q] = 0.f;

    float m0 = -1e30f, m1 = -1e30f, l0 = 0.f, l1 = 0.f;

    for (int kt = 0; kt < S_LEN / 64; kt++) {
        __syncthreads();   // previous tile's P/V reads done before overwrite

        // cooperative K,V tile load (+tf32 convert)
        #pragma unroll
        for (int p = 0; p < 8; p++) {
            const int f  = tid + 128 * p;
            const int r  = f >> 4;
            const int c4 = (f & 15) * 4;
            const float* kp = base + (size_t)(kt * 64 + r) * QKV_N + ho + DK + c4;
            const float4 kv = *(const float4*)kp;
            const float4 vv = *(const float4*)(kp + DK);
            unsigned* kd = KPs + r * KS_STR + c4;
            kd[0] = f2tf(kv.x); kd[1] = f2tf(kv.y);
            kd[2] = f2tf(kv.z); kd[3] = f2tf(kv.w);
            unsigned* vd = Vs + r * VS_STR + c4;
            vd[0] = f2tf(vv.x); vd[1] = f2tf(vv.y);
            vd[2] = f2tf(vv.z); vd[3] = f2tf(vv.w);
        }
        __syncthreads();

        // S = Q @ K^T  (16 rows x 64 keys per warp)
        float sAcc[8][4];
        #pragma unroll
        for (int j = 0; j < 8; j++) {
            sAcc[j][0] = sAcc[j][1] = sAcc[j][2] = sAcc[j][3] = 0.f;
            #pragma unroll
            for (int kk = 0; kk < 8; kk++) {
                const unsigned b0 = KPs[(8 * j + lr) * KS_STR + 8 * kk + lc];
                const unsigned b1 = KPs[(8 * j + lr) * KS_STR + 8 * kk + lc + 4];
                mma_tf32(sAcc[j], Qf[kk], b0, b1);
            }
        }

        __syncthreads();   // all warps done reading K before P overwrites it

        // online softmax (rows lr and lr+8 of this warp's 16)
        float mx0 = -1e30f, mx1 = -1e30f;
        #pragma unroll
        for (int j = 0; j < 8; j++) {
            mx0 = fmaxf(mx0, fmaxf(sAcc[j][0], sAcc[j][1]));
            mx1 = fmaxf(mx1, fmaxf(sAcc[j][2], sAcc[j][3]));
        }
        mx0 = fmaxf(mx0, __shfl_xor_sync(0xffffffffu, mx0, 1));
        mx0 = fmaxf(mx0, __shfl_xor_sync(0xffffffffu, mx0, 2));
        mx1 = fmaxf(mx1, __shfl_xor_sync(0xffffffffu, mx1, 1));
        mx1 = fmaxf(mx1, __shfl_xor_sync(0xffffffffu, mx1, 2));

        const float mn0 = fmaxf(m0, mx0), mn1 = fmaxf(m1, mx1);
        const float cor0 = __expf(m0 - mn0), cor1 = __expf(m1 - mn1);
        m0 = mn0; m1 = mn1;

        float s0 = 0.f, s1 = 0.f;
        #pragma unroll
        for (int j = 0; j < 8; j++) {
            sAcc[j][0] = __expf(sAcc[j][0] - mn0); s0 += sAcc[j][0];
            sAcc[j][1] = __expf(sAcc[j][1] - mn0); s0 += sAcc[j][1];
            sAcc[j][2] = __expf(sAcc[j][2] - mn1); s1 += sAcc[j][2];
            sAcc[j][3] = __expf(sAcc[j][3] - mn1); s1 += sAcc[j][3];
        }
        s0 += __shfl_xor_sync(0xffffffffu, s0, 1);
        s0 += __shfl_xor_sync(0xffffffffu, s0, 2);
        s1 += __shfl_xor_sync(0xffffffffu, s1, 1);
        s1 += __shfl_xor_sync(0xffffffffu, s1, 2);
        l0 = l0 * cor0 + s0;
        l1 = l1 * cor1 + s1;

        #pragma unroll
        for (int j = 0; j < 8; j++) {
            oAcc[j][0] *= cor0; oAcc[j][1] *= cor0;
            oAcc[j][2] *= cor1; oAcc[j][3] *= cor1;
        }

        // bounce P through smem (warp-local rows) to get A-fragment layout
        const int pr0 = (wid * 16 + lr) * KS_STR;
        const int pr1 = pr0 + 8 * KS_STR;
        #pragma unroll
        for (int j = 0; j < 8; j++) {
            const int colo = 8 * j + 2 * lc;
            uint2 v0 = make_uint2(f2tf(sAcc[j][0]), f2tf(sAcc[j][1]));
            uint2 v1 = make_uint2(f2tf(sAcc[j][2]), f2tf(sAcc[j][3]));
            *(uint2*)(KPs + pr0 + colo) = v0;
            *(uint2*)(KPs + pr1 + colo) = v1;
        }
        __syncwarp();

        unsigned pf[8][4];
        #pragma unroll
        for (int kk = 0; kk < 8; kk++) {
            pf[kk][0] = KPs[pr0 + 8 * kk + lc];
            pf[kk][1] = KPs[pr1 + 8 * kk + lc];
            pf[kk][2] = KPs[pr0 + 8 * kk + lc + 4];
            pf[kk][3] = KPs[pr1 + 8 * kk + lc + 4];
        }

        // O += P @ V
        #pragma unroll
        for (int j = 0; j < 8; j++) {
            #pragma unroll
            for (int kk = 0; kk < 8; kk++) {
                const unsigned b0 = Vs[(8 * kk + lc) * VS_STR + 8 * j + lr];
                const unsigned b1 = Vs[(8 * kk + lc + 4) * VS_STR + 8 * j + lr];
                mma_tf32(oAcc[j], pf[kk], b0, b1);
            }
        }
    }

    // epilogue: normalize, write head-interleaved ctx
    const float inv0 = 1.f / l0, inv1 = 1.f / l1;
    float* orow0 = g_ctx + (size_t)(b * S_LEN + q0 + wid * 16 + lr) * D_MODEL + h * DK;
    float* orow1 = orow0 + (size_t)8 * D_MODEL;
    #pragma unroll
    for (int j = 0; j < 8; j++) {
        const int colo = 8 * j + 2 * lc;
        *(float2*)(orow0 + colo) = make_float2(oAcc[j][0] * inv0, oAcc[j][1] * inv0);
        *(float2*)(orow1 + colo) = make_float2(oAcc[j][2] * inv1, oAcc[j][3] * inv1);
    }
}

// ---------------------------------------------------------------------------
extern "C" void kernel_launch(void* const* d_in, const int* in_sizes, int n_in,
                              void* d_out, int out_size)
{
    (void)in_sizes; (void)n_in; (void)out_size;
    const float* x     = (const float*)d_in[0];
    const float* W_qkv = (const float*)d_in[1];
    const float* b_qkv = (const float*)d_in[2];
    const float* W_o   = (const float*)d_in[3];
    const float* b_o   = (const float*)d_in[4];
    float* out = (float*)d_out;

    k_gemm_qkv<<<dim3(QKV_N / 128, M_ROWS / 128), 256>>>(x, W_qkv, b_qkv);
    k_attn_tc<<<dim3(B_SZ * NHEADS, S_LEN / 64), 128>>>();
    k_gemm_out<<<dim3(D_MODEL / 128, M_ROWS / 128), 256>>>(W_o, b_o, out);
}

// round 3
// speedup vs baseline: 4.2992x; 1.0020x over previous
#include <cuda_runtime.h>

#define B_SZ    2
#define S_LEN   2048
#define D_MODEL 1024
#define NHEADS  16
#define DK      64
#define M_ROWS  (B_SZ * S_LEN)     // 4096
#define QKV_N   (3 * D_MODEL)      // 3072

// Scratch (alloc-free: __device__ globals)
__device__ float g_qkv[(size_t)M_ROWS * QKV_N];   // (b*s, 3*d)
__device__ float g_ctx[(size_t)M_ROWS * D_MODEL]; // (b*s, d) head-interleaved

// ---------------------------------------------------------------------------
// helpers
// ---------------------------------------------------------------------------
__device__ __forceinline__ unsigned f2tf(float f) {
    unsigned u;
    asm("cvt.rna.tf32.f32 %0, %1;" : "=r"(u) : "f"(f));
    return u;
}

__device__ __forceinline__ void mma_tf32(float* c, const unsigned* a,
                                         unsigned b0, unsigned b1) {
    asm volatile(
        "mma.sync.aligned.m16n8k8.row.col.f32.tf32.tf32.f32 "
        "{%0,%1,%2,%3}, {%4,%5,%6,%7}, {%8,%9}, {%0,%1,%2,%3};\n"
        : "+f"(c[0]), "+f"(c[1]), "+f"(c[2]), "+f"(c[3])
        : "r"(a[0]), "r"(a[1]), "r"(a[2]), "r"(a[3]), "r"(b0), "r"(b1));
}

// ---------------------------------------------------------------------------
// TF32 GEMM: C[M,N] = A[M,K] @ B[K,N] + bias[N]
// Block 128x128, BK=16, 256 threads = 8 warps (4 along M, 2 along N),
// warp tile 32x64. Double-buffered smem. Padded strides:
//   As stride 20  (== 4 mod 32): A-frag loads conflict-free
//   Bs stride 136 (== 8 mod 32): B-frag loads conflict-free
// ---------------------------------------------------------------------------
#define AS_STR 20
#define BS_STR 136

__device__ __forceinline__ void gemm_tf32_body(const float* __restrict__ A,
                                               const float* __restrict__ B,
                                               const float* __restrict__ bias,
                                               float* __restrict__ C,
                                               int M, int N, int K)
{
    __shared__ unsigned As[2][128 * AS_STR];
    __shared__ unsigned Bs[2][16 * BS_STR];

    const int tid  = threadIdx.x;
    const int wid  = tid >> 5;
    const int lane = tid & 31;
    const int lr   = lane >> 2;   // 0..7
    const int lc   = lane & 3;    // 0..3
    const int wm   = (wid & 3) * 32;
    const int wn   = (wid >> 2) * 64;
    const int bm   = blockIdx.y * 128;
    const int bn   = blockIdx.x * 128;

    float acc[2][8][4];
    #pragma unroll
    for (int i = 0; i < 2; i++)
        #pragma unroll
        for (int j = 0; j < 8; j++)
            #pragma unroll
            for (int q = 0; q < 4; q++) acc[i][j][q] = 0.f;

    float4 aR[2], bR[2];

    // global-load index precompute
    const int aRow0 = tid >> 2,  aCv0 = tid & 3;           // f = tid
    const int aRow1 = (tid + 256) >> 2, aCv1 = tid & 3;    // f = tid+256
    const int bRow0 = tid >> 5,  bCv0 = tid & 31;
    const int bRow1 = (tid + 256) >> 5, bCv1 = tid & 31;

    auto ldg = [&](int k0) {
        aR[0] = *(const float4*)(A + (size_t)(bm + aRow0) * K + k0 + aCv0 * 4);
        aR[1] = *(const float4*)(A + (size_t)(bm + aRow1) * K + k0 + aCv1 * 4);
        bR[0] = *(const float4*)(B + (size_t)(k0 + bRow0) * N + bn + bCv0 * 4);
        bR[1] = *(const float4*)(B + (size_t)(k0 + bRow1) * N + bn + bCv1 * 4);
    };
    auto sts = [&](int buf) {
        unsigned* a0 = &As[buf][aRow0 * AS_STR + aCv0 * 4];
        a0[0] = f2tf(aR[0].x); a0[1] = f2tf(aR[0].y);
        a0[2] = f2tf(aR[0].z); a0[3] = f2tf(aR[0].w);
        unsigned* a1 = &As[buf][aRow1 * AS_STR + aCv1 * 4];
        a1[0] = f2tf(aR[1].x); a1[1] = f2tf(aR[1].y);
        a1[2] = f2tf(aR[1].z); a1[3] = f2tf(aR[1].w);
        unsigned* b0 = &Bs[buf][bRow0 * BS_STR + bCv0 * 4];
        b0[0] = f2tf(bR[0].x); b0[1] = f2tf(bR[0].y);
        b0[2] = f2tf(bR[0].z); b0[3] = f2tf(bR[0].w);
        unsigned* b1 = &Bs[buf][bRow1 * BS_STR + bCv1 * 4];
        b1[0] = f2tf(bR[1].x); b1[1] = f2tf(bR[1].y);
        b1[2] = f2tf(bR[1].z); b1[3] = f2tf(bR[1].w);
    };

    ldg(0);
    sts(0);
    __syncthreads();

    const int nT = K / 16;
    for (int t = 0; t < nT; t++) {
        const int buf = t & 1;
        const bool more = (t + 1 < nT);
        if (more) ldg((t + 1) * 16);

        #pragma unroll
        for (int kk = 0; kk < 2; kk++) {
            unsigned af[2][4];
            #pragma unroll
            for (int i = 0; i < 2; i++) {
                const int m = wm + 16 * i + lr;
                af[i][0] = As[buf][m * AS_STR + 8 * kk + lc];
                af[i][1] = As[buf][(m + 8) * AS_STR + 8 * kk + lc];
                af[i][2] = As[buf][m * AS_STR + 8 * kk + lc + 4];
                af[i][3] = As[buf][(m + 8) * AS_STR + 8 * kk + lc + 4];
            }
            #pragma unroll
            for (int j = 0; j < 8; j++) {
                const unsigned b0 = Bs[buf][(8 * kk + lc) * BS_STR + wn + 8 * j + lr];
                const unsigned b1 = Bs[buf][(8 * kk + lc + 4) * BS_STR + wn + 8 * j + lr];
                mma_tf32(acc[0][j], af[0], b0, b1);
                mma_tf32(acc[1][j], af[1], b0, b1);
            }
        }

        if (more) sts(buf ^ 1);
        __syncthreads();
    }

    // epilogue: bias + store
    #pragma unroll
    for (int j = 0; j < 8; j++) {
        const int col = bn + wn + 8 * j + 2 * lc;
        const float bs0 = bias[col], bs1 = bias[col + 1];
        #pragma unroll
        for (int i = 0; i < 2; i++) {
            const int row = bm + wm + 16 * i + lr;
            float2 r0 = make_float2(acc[i][j][0] + bs0, acc[i][j][1] + bs1);
            float2 r1 = make_float2(acc[i][j][2] + bs0, acc[i][j][3] + bs1);
            *(float2*)(C + (size_t)row * N + col) = r0;
            *(float2*)(C + (size_t)(row + 8) * N + col) = r1;
        }
    }
}

__global__ void __launch_bounds__(256)
k_gemm_qkv(const float* __restrict__ x, const float* __restrict__ W,
           const float* __restrict__ bias)
{
    gemm_tf32_body(x, W, bias, g_qkv, M_ROWS, QKV_N, D_MODEL);
}

__global__ void __launch_bounds__(256)
k_gemm_out(const float* __restrict__ W, const float* __restrict__ bias,
           float* __restrict__ out)
{
    gemm_tf32_body(g_ctx, W, bias, out, M_ROWS, D_MODEL, D_MODEL);
}

// ---------------------------------------------------------------------------
// Flash attention with tf32 tensor cores.
// Block = 128 threads (4 warps), 64 query rows; each warp owns 16 rows.
// Q fragments live in registers (scale 1/8 folded in). Per 64-key tile:
//   S = Q@K^T (mma) -> online softmax on C-fragments -> P bounced through
//   smem (aliased onto K buffer) to become A-fragments -> O += P@V (mma).
// Padded strides: K/P stride 68 (==4 mod 32), V stride 72 (==8 mod 32).
// ---------------------------------------------------------------------------
#define KS_STR 68
#define VS_STR 72

__global__ void __launch_bounds__(128)
k_attn_tc()
{
    __shared__ unsigned KPs[64 * KS_STR];  // K tile, reused as P buffer
    __shared__ unsigned Vs [64 * VS_STR];

    const int tid  = threadIdx.x;
    const int wid  = tid >> 5;
    const int lane = tid & 31;
    const int lr   = lane >> 2;
    const int lc   = lane & 3;
    const int bh   = blockIdx.x;
    const int b    = bh >> 4;
    const int h    = bh & 15;
    const int q0   = blockIdx.y * 64;

    const float* base = g_qkv + (size_t)b * S_LEN * QKV_N;
    const int ho = h * (3 * DK);

    // Q fragments (register-resident for whole kernel), pre-scaled by 1/8
    unsigned Qf[8][4];
    {
        const float* qr0 = base + (size_t)(q0 + wid * 16 + lr) * QKV_N + ho;
        const float* qr1 = qr0 + (size_t)8 * QKV_N;
        #pragma unroll
        for (int kk = 0; kk < 8; kk++) {
            Qf[kk][0] = f2tf(0.125f * qr0[8 * kk + lc]);
            Qf[kk][1] = f2tf(0.125f * qr1[8 * kk + lc]);
            Qf[kk][2] = f2tf(0.125f * qr0[8 * kk + lc + 4]);
            Qf[kk][3] = f2tf(0.125f * qr1[8 * kk + lc + 4]);
        }
    }

    float oAcc[8][4];
    #pragma unroll
    for (int j = 0; j < 8; j++)
        #pragma unroll
        for (int q = 0; q < 4; q++) oAcc[j][q] = 0.f;

    float m0 = -1e30f, m1 = -1e30f, l0 = 0.f, l1 = 0.f;

    for (int kt = 0; kt < S_LEN / 64; kt++) {
        __syncthreads();   // previous tile's P/V reads done before overwrite

        // cooperative K,V tile load (+tf32 convert)
        #pragma unroll
        for (int p = 0; p < 8; p++) {
            const int f  = tid + 128 * p;
            const int r  = f >> 4;
            const int c4 = (f & 15) * 4;
            const float* kp = base + (size_t)(kt * 64 + r) * QKV_N + ho + DK + c4;
            const float4 kv = *(const float4*)kp;
            const float4 vv = *(const float4*)(kp + DK);
            unsigned* kd = KPs + r * KS_STR + c4;
            kd[0] = f2tf(kv.x); kd[1] = f2tf(kv.y);
            kd[2] = f2tf(kv.z); kd[3] = f2tf(kv.w);
            unsigned* vd = Vs + r * VS_STR + c4;
            vd[0] = f2tf(vv.x); vd[1] = f2tf(vv.y);
            vd[2] = f2tf(vv.z); vd[3] = f2tf(vv.w);
        }
        __syncthreads();

        // S = Q @ K^T  (16 rows x 64 keys per warp)
        float sAcc[8][4];
        #pragma unroll
        for (int j = 0; j < 8; j++) {
            sAcc[j][0] = sAcc[j][1] = sAcc[j][2] = sAcc[j][3] = 0.f;
            #pragma unroll
            for (int kk = 0; kk < 8; kk++) {
                const unsigned b0 = KPs[(8 * j + lr) * KS_STR + 8 * kk + lc];
                const unsigned b1 = KPs[(8 * j + lr) * KS_STR + 8 * kk + lc + 4];
                mma_tf32(sAcc[j], Qf[kk], b0, b1);
            }
        }

        __syncthreads();   // all warps done reading K before P overwrites it

        // online softmax (rows lr and lr+8 of this warp's 16)
        float mx0 = -1e30f, mx1 = -1e30f;
        #pragma unroll
        for (int j = 0; j < 8; j++) {
            mx0 = fmaxf(mx0, fmaxf(sAcc[j][0], sAcc[j][1]));
            mx1 = fmaxf(mx1, fmaxf(sAcc[j][2], sAcc[j][3]));
        }
        mx0 = fmaxf(mx0, __shfl_xor_sync(0xffffffffu, mx0, 1));
        mx0 = fmaxf(mx0, __shfl_xor_sync(0xffffffffu, mx0, 2));
        mx1 = fmaxf(mx1, __shfl_xor_sync(0xffffffffu, mx1, 1));
        mx1 = fmaxf(mx1, __shfl_xor_sync(0xffffffffu, mx1, 2));

        const float mn0 = fmaxf(m0, mx0), mn1 = fmaxf(m1, mx1);
        const float cor0 = __expf(m0 - mn0), cor1 = __expf(m1 - mn1);
        m0 = mn0; m1 = mn1;

        float s0 = 0.f, s1 = 0.f;
        #pragma unroll
        for (int j = 0; j < 8; j++) {
            sAcc[j][0] = __expf(sAcc[j][0] - mn0); s0 += sAcc[j][0];
            sAcc[j][1] = __expf(sAcc[j][1] - mn0); s0 += sAcc[j][1];
            sAcc[j][2] = __expf(sAcc[j][2] - mn1); s1 += sAcc[j][2];
            sAcc[j][3] = __expf(sAcc[j][3] - mn1); s1 += sAcc[j][3];
        }
        s0 += __shfl_xor_sync(0xffffffffu, s0, 1);
        s0 += __shfl_xor_sync(0xffffffffu, s0, 2);
        s1 += __shfl_xor_sync(0xffffffffu, s1, 1);
        s1 += __shfl_xor_sync(0xffffffffu, s1, 2);
        l0 = l0 * cor0 + s0;
        l1 = l1 * cor1 + s1;

        #pragma unroll
        for (int j = 0; j < 8; j++) {
            oAcc[j][0] *= cor0; oAcc[j][1] *= cor0;
            oAcc[j][2] *= cor1; oAcc[j][3] *= cor1;
        }

        // bounce P through smem (warp-local rows) to get A-fragment layout
        const int pr0 = (wid * 16 + lr) * KS_STR;
        const int pr1 = pr0 + 8 * KS_STR;
        #pragma unroll
        for (int j = 0; j < 8; j++) {
            const int colo = 8 * j + 2 * lc;
            uint2 v0 = make_uint2(f2tf(sAcc[j][0]), f2tf(sAcc[j][1]));
            uint2 v1 = make_uint2(f2tf(sAcc[j][2]), f2tf(sAcc[j][3]));
            *(uint2*)(KPs + pr0 + colo) = v0;
            *(uint2*)(KPs + pr1 + colo) = v1;
        }
        __syncwarp();

        unsigned pf[8][4];
        #pragma unroll
        for (int kk = 0; kk < 8; kk++) {
            pf[kk][0] = KPs[pr0 + 8 * kk + lc];
            pf[kk][1] = KPs[pr1 + 8 * kk + lc];
            pf[kk][2] = KPs[pr0 + 8 * kk + lc + 4];
            pf[kk][3] = KPs[pr1 + 8 * kk + lc + 4];
        }

        // O += P @ V
        #pragma unroll
        for (int j = 0; j < 8; j++) {
            #pragma unroll
            for (int kk = 0; kk < 8; kk++) {
                const unsigned b0 = Vs[(8 * kk + lc) * VS_STR + 8 * j + lr];
                const unsigned b1 = Vs[(8 * kk + lc + 4) * VS_STR + 8 * j + lr];
                mma_tf32(oAcc[j], pf[kk], b0, b1);
            }
        }
    }

    // epilogue: normalize, write head-interleaved ctx
    const float inv0 = 1.f / l0, inv1 = 1.f / l1;
    float* orow0 = g_ctx + (size_t)(b * S_LEN + q0 + wid * 16 + lr) * D_MODEL + h * DK;
    float* orow1 = orow0 + (size_t)8 * D_MODEL;
    #pragma unroll
    for (int j = 0; j < 8; j++) {
        const int colo = 8 * j + 2 * lc;
        *(float2*)(orow0 + colo) = make_float2(oAcc[j][0] * inv0, oAcc[j][1] * inv0);
        *(float2*)(orow1 + colo) = make_float2(oAcc[j][2] * inv1, oAcc[j][3] * inv1);
    }
}

// ---------------------------------------------------------------------------
extern "C" void kernel_launch(void* const* d_in, const int* in_sizes, int n_in,
                              void* d_out, int out_size)
{
    (void)in_sizes; (void)n_in; (void)out_size;
    const float* x     = (const float*)d_in[0];
    const float* W_qkv = (const float*)d_in[1];
    const float* b_qkv = (const float*)d_in[2];
    const float* W_o   = (const float*)d_in[3];
    const float* b_o   = (const float*)d_in[4];
    float* out = (float*)d_out;

    k_gemm_qkv<<<dim3(QKV_N / 128, M_ROWS / 128), 256>>>(x, W_qkv, b_qkv);
    k_attn_tc<<<dim3(B_SZ * NHEADS, S_LEN / 64), 128>>>();
    k_gemm_out<<<dim3(D_MODEL / 128, M_ROWS / 128), 256>>>(W_o, b_o, out);
}